// round 2
// baseline (speedup 1.0000x reference)
#include <cuda_runtime.h>
#include <cstdint>

// Problem constants (from reference setup_inputs)
#define BB 16
#define TT 4096
#define DD 768
#define SS 64
#define D4 (DD / 4)          // 192 float4 lanes per row
#define OUT_VEC ((size_t)BB * 2 * SS * DD)   // 1,572,864 floats

// One block per (b, s) segment. 192 threads; thread tid owns float4 column tid.
__global__ __launch_bounds__(192) void pooling_kernel(
    const float* __restrict__ wv,           // [B, T, D]
    const int* __restrict__ rep_ids,        // [B, S]
    const int* __restrict__ rep_mask,       // [B, S] bool marshaled as int32
    const int* __restrict__ lens,           // [B, S]
    const int* __restrict__ len_mask,       // [B, S] bool marshaled as int32
    float* __restrict__ out)                // [B, 2S, D]
{
    const int blk = blockIdx.x;             // b*S + s
    const int b = blk / SS;
    const int s = blk % SS;
    const int tid = threadIdx.x;            // 0..191

    __shared__ int sh_bounds[2];
    __shared__ float sh_cnt[192];
    __shared__ int sh_empty;

    if (tid == 0) {
        const int* lrow = lens + b * SS;
        int start = 0;
        #pragma unroll 8
        for (int i = 0; i < SS; i++) {
            int li = lrow[i];
            if (i < s) start += li;
        }
        long long endl = (long long)start + (long long)lrow[s];
        if (start < 0) start = 0;
        if (start > TT) start = TT;
        int end = (endl > TT) ? TT : (int)endl;
        if (end < start) end = start;
        sh_bounds[0] = start;
        sh_bounds[1] = end;
    }
    __syncthreads();
    const int start = sh_bounds[0];
    const int end   = sh_bounds[1];

    const float4* base = reinterpret_cast<const float4*>(wv + (size_t)b * TT * DD);

    float sx = 0.f, sy = 0.f, sz = 0.f, sw = 0.f;
    float cx = 0.f, cy = 0.f, cz = 0.f, cw = 0.f;

    #pragma unroll 4
    for (int t = start; t < end; t++) {
        float4 v = __ldg(base + (size_t)t * D4 + tid);
        sx += v.x; sy += v.y; sz += v.z; sw += v.w;
        cx += (v.x != 0.f) ? 1.f : 0.f;
        cy += (v.y != 0.f) ? 1.f : 0.f;
        cz += (v.z != 0.f) ? 1.f : 0.f;
        cw += (v.w != 0.f) ? 1.f : 0.f;
    }

    // Whole-segment emptiness check (seg_cnt.sum(-1) == 0)
    sh_cnt[tid] = cx + cy + cz + cw;
    __syncthreads();
    if (tid == 0) {
        float tot = 0.f;
        #pragma unroll 8
        for (int i = 0; i < 192; i++) tot += sh_cnt[i];
        sh_empty = (tot == 0.f) ? 1 : 0;
    }
    __syncthreads();
    const bool empty = (sh_empty != 0);

    const float lm = (len_mask[b * SS + s] != 0) ? 1.f : 0.f;

    float4 o;
    if (empty) {
        // fallback to word_vectors[0, 0, :]
        float4 w0 = __ldg(reinterpret_cast<const float4*>(wv) + tid);
        o.x = w0.x * lm; o.y = w0.y * lm; o.z = w0.z * lm; o.w = w0.w * lm;
    } else {
        float dx = (cx == 0.f) ? 1.f : cx;
        float dy = (cy == 0.f) ? 1.f : cy;
        float dz = (cz == 0.f) ? 1.f : cz;
        float dw = (cw == 0.f) ? 1.f : cw;
        o.x = (sx / dx) * lm;
        o.y = (sy / dy) * lm;
        o.z = (sz / dz) * lm;
        o.w = (sw / dw) * lm;
    }
    // mean_vec goes to out[b, S + s, :]
    float4* out4 = reinterpret_cast<float4*>(out);
    out4[((size_t)b * 2 * SS + SS + s) * D4 + tid] = o;

    // rep_vec: gather word_vectors[b, rep_ids[b,s], :] * rep_mask
    int rid = rep_ids[b * SS + s];
    if (rid < 0) rid = 0;
    if (rid >= TT) rid = TT - 1;
    const float rm = (rep_mask[b * SS + s] != 0) ? 1.f : 0.f;
    float4 r = __ldg(base + (size_t)rid * D4 + tid);
    r.x *= rm; r.y *= rm; r.z *= rm; r.w *= rm;
    out4[((size_t)b * 2 * SS + s) * D4 + tid] = r;
}

// If the harness flattens the tuple (vector, mask) into one buffer,
// append the mask (as output dtype float) after the vector.
__global__ void mask_tail_kernel(
    const int* __restrict__ rep_mask,
    const int* __restrict__ len_mask,
    float* __restrict__ out_tail)           // [B, 2S]
{
    int i = blockIdx.x * blockDim.x + threadIdx.x;   // 0 .. B*2S-1
    if (i >= BB * 2 * SS) return;
    int b = i / (2 * SS);
    int c = i % (2 * SS);
    int m = (c < SS) ? rep_mask[b * SS + c] : len_mask[b * SS + (c - SS)];
    out_tail[i] = m ? 1.f : 0.f;
}

extern "C" void kernel_launch(void* const* d_in, const int* in_sizes, int n_in,
                              void* d_out, int out_size)
{
    const float* wv       = (const float*)d_in[0];
    const int*   rep_ids  = (const int*)d_in[1];
    const int*   rep_mask = (const int*)d_in[2];
    const int*   lens     = (const int*)d_in[3];
    const int*   len_mask = (const int*)d_in[4];
    float* out = (float*)d_out;

    pooling_kernel<<<BB * SS, 192>>>(wv, rep_ids, rep_mask, lens, len_mask, out);

    if ((size_t)out_size > OUT_VEC) {
        // harness expects the flattened tuple; append output_mask
        int n = BB * 2 * SS;
        mask_tail_kernel<<<(n + 255) / 256, 256>>>(rep_mask, len_mask, out + OUT_VEC);
    }
}

// round 3
// speedup vs baseline: 1.0394x; 1.0394x over previous
#include <cuda_runtime.h>
#include <cstdint>

// Problem constants (from reference setup_inputs)
#define BB 16
#define TT 4096
#define DD 768
#define SS 64
#define D4 (DD / 4)          // 192 float4 lanes per row
#define OUT_VEC ((size_t)BB * 2 * SS * DD)   // 1,572,864 floats

// One block per (b, s) segment. 192 threads; thread tid owns float4 column tid.
// Also writes its 2 entries of the flattened output mask tail (if present).
__global__ __launch_bounds__(192) void pooling_kernel(
    const float* __restrict__ wv,           // [B, T, D]
    const int* __restrict__ rep_ids,        // [B, S]
    const int* __restrict__ rep_mask,       // [B, S] bool marshaled as int32
    const int* __restrict__ lens,           // [B, S]
    const int* __restrict__ len_mask,       // [B, S] bool marshaled as int32
    float* __restrict__ out,                // [B, 2S, D] (+ optional [B, 2S] mask tail)
    int write_mask_tail)
{
    const int blk = blockIdx.x;             // b*S + s
    const int b = blk / SS;
    const int s = blk % SS;
    const int tid = threadIdx.x;            // 0..191

    __shared__ int sh_bounds[2];
    __shared__ float sh_cnt[192];
    __shared__ int sh_empty;

    if (tid == 0) {
        const int* lrow = lens + b * SS;
        int start = 0;
        #pragma unroll 8
        for (int i = 0; i < SS; i++) {
            int li = lrow[i];
            if (i < s) start += li;
        }
        long long endl = (long long)start + (long long)lrow[s];
        if (start < 0) start = 0;
        if (start > TT) start = TT;
        int end = (endl > TT) ? TT : (int)endl;
        if (end < start) end = start;
        sh_bounds[0] = start;
        sh_bounds[1] = end;
    }
    __syncthreads();
    const int start = sh_bounds[0];
    const int end   = sh_bounds[1];

    const float4* base = reinterpret_cast<const float4*>(wv + (size_t)b * TT * DD);

    float sx = 0.f, sy = 0.f, sz = 0.f, sw = 0.f;
    float cx = 0.f, cy = 0.f, cz = 0.f, cw = 0.f;

    #pragma unroll 8
    for (int t = start; t < end; t++) {
        float4 v = __ldg(base + (size_t)t * D4 + tid);
        sx += v.x; sy += v.y; sz += v.z; sw += v.w;
        cx += (v.x != 0.f) ? 1.f : 0.f;
        cy += (v.y != 0.f) ? 1.f : 0.f;
        cz += (v.z != 0.f) ? 1.f : 0.f;
        cw += (v.w != 0.f) ? 1.f : 0.f;
    }

    // Whole-segment emptiness check (seg_cnt.sum(-1) == 0)
    sh_cnt[tid] = cx + cy + cz + cw;
    __syncthreads();
    if (tid == 0) {
        float tot = 0.f;
        #pragma unroll 8
        for (int i = 0; i < 192; i++) tot += sh_cnt[i];
        sh_empty = (tot == 0.f) ? 1 : 0;
    }
    __syncthreads();
    const bool empty = (sh_empty != 0);

    const int lmi = len_mask[b * SS + s];
    const int rmi = rep_mask[b * SS + s];
    const float lm = (lmi != 0) ? 1.f : 0.f;
    const float rm = (rmi != 0) ? 1.f : 0.f;

    float4 o;
    if (empty) {
        // fallback to word_vectors[0, 0, :]
        float4 w0 = __ldg(reinterpret_cast<const float4*>(wv) + tid);
        o.x = w0.x * lm; o.y = w0.y * lm; o.z = w0.z * lm; o.w = w0.w * lm;
    } else {
        float dx = (cx == 0.f) ? 1.f : cx;
        float dy = (cy == 0.f) ? 1.f : cy;
        float dz = (cz == 0.f) ? 1.f : cz;
        float dw = (cw == 0.f) ? 1.f : cw;
        o.x = (sx / dx) * lm;
        o.y = (sy / dy) * lm;
        o.z = (sz / dz) * lm;
        o.w = (sw / dw) * lm;
    }
    // mean_vec goes to out[b, S + s, :]
    float4* out4 = reinterpret_cast<float4*>(out);
    out4[((size_t)b * 2 * SS + SS + s) * D4 + tid] = o;

    // rep_vec: gather word_vectors[b, rep_ids[b,s], :] * rep_mask
    int rid = rep_ids[b * SS + s];
    if (rid < 0) rid = 0;
    if (rid >= TT) rid = TT - 1;
    float4 r = __ldg(base + (size_t)rid * D4 + tid);
    r.x *= rm; r.y *= rm; r.z *= rm; r.w *= rm;
    out4[((size_t)b * 2 * SS + s) * D4 + tid] = r;

    // output mask tail (flattened tuple): out_tail[b, c] with c in [0, 2S)
    if (write_mask_tail) {
        float* out_tail = out + OUT_VEC;
        if (tid == 0) out_tail[b * 2 * SS + s]      = rm;   // rep mask half
        if (tid == 1) out_tail[b * 2 * SS + SS + s] = lm;   // len mask half
    }
}

extern "C" void kernel_launch(void* const* d_in, const int* in_sizes, int n_in,
                              void* d_out, int out_size)
{
    const float* wv       = (const float*)d_in[0];
    const int*   rep_ids  = (const int*)d_in[1];
    const int*   rep_mask = (const int*)d_in[2];
    const int*   lens     = (const int*)d_in[3];
    const int*   len_mask = (const int*)d_in[4];
    float* out = (float*)d_out;

    int write_mask_tail = ((size_t)out_size > OUT_VEC) ? 1 : 0;
    pooling_kernel<<<BB * SS, 192>>>(wv, rep_ids, rep_mask, lens, len_mask, out,
                                     write_mask_tail);
}

// round 4
// speedup vs baseline: 1.0934x; 1.0520x over previous
#include <cuda_runtime.h>
#include <cstdint>

// Problem constants (from reference setup_inputs)
#define BB 16
#define TT 4096
#define DD 768
#define SS 64
#define D4 (DD / 4)          // 192 float4 lanes per row
#define OUT_VEC ((size_t)BB * 2 * SS * DD)   // 1,572,864 floats

// One block per (b, s) segment. 192 threads; thread tid owns float4 column tid.
// Token loop is batched x4 with independent loads for MLP=4.
__global__ __launch_bounds__(192, 7) void pooling_kernel(
    const float* __restrict__ wv,           // [B, T, D]
    const int* __restrict__ rep_ids,        // [B, S]
    const int* __restrict__ rep_mask,       // [B, S] bool marshaled as int32
    const int* __restrict__ lens,           // [B, S]
    const int* __restrict__ len_mask,       // [B, S] bool marshaled as int32
    float* __restrict__ out,                // [B, 2S, D] (+ optional [B, 2S] mask tail)
    int write_mask_tail)
{
    const int blk = blockIdx.x;             // b*S + s
    const int b = blk / SS;
    const int s = blk % SS;
    const int tid = threadIdx.x;            // 0..191

    __shared__ int sh_bounds[2];
    __shared__ float sh_cnt[192];
    __shared__ int sh_empty;

    if (tid == 0) {
        const int* lrow = lens + b * SS;
        int start = 0;
        #pragma unroll 8
        for (int i = 0; i < SS; i++) {
            int li = lrow[i];
            if (i < s) start += li;
        }
        long long endl = (long long)start + (long long)lrow[s];
        if (start < 0) start = 0;
        if (start > TT) start = TT;
        int end = (endl > TT) ? TT : (int)endl;
        if (end < start) end = start;
        sh_bounds[0] = start;
        sh_bounds[1] = end;
    }
    __syncthreads();
    const int start = sh_bounds[0];
    const int end   = sh_bounds[1];

    const float4* base = reinterpret_cast<const float4*>(wv + (size_t)b * TT * DD);
    const float4* p = base + (size_t)start * D4 + tid;

    float sx = 0.f, sy = 0.f, sz = 0.f, sw = 0.f;
    float cx = 0.f, cy = 0.f, cz = 0.f, cw = 0.f;

    int t = start;
    // Main loop: 4 tokens per iteration, 4 independent LDG.128 in flight.
    for (; t + 4 <= end; t += 4, p += 4 * D4) {
        float4 v0 = __ldg(p);
        float4 v1 = __ldg(p + D4);
        float4 v2 = __ldg(p + 2 * D4);
        float4 v3 = __ldg(p + 3 * D4);

        sx += v0.x + v1.x + v2.x + v3.x;
        sy += v0.y + v1.y + v2.y + v3.y;
        sz += v0.z + v1.z + v2.z + v3.z;
        sw += v0.w + v1.w + v2.w + v3.w;

        cx += ((v0.x != 0.f) ? 1.f : 0.f) + ((v1.x != 0.f) ? 1.f : 0.f)
            + ((v2.x != 0.f) ? 1.f : 0.f) + ((v3.x != 0.f) ? 1.f : 0.f);
        cy += ((v0.y != 0.f) ? 1.f : 0.f) + ((v1.y != 0.f) ? 1.f : 0.f)
            + ((v2.y != 0.f) ? 1.f : 0.f) + ((v3.y != 0.f) ? 1.f : 0.f);
        cz += ((v0.z != 0.f) ? 1.f : 0.f) + ((v1.z != 0.f) ? 1.f : 0.f)
            + ((v2.z != 0.f) ? 1.f : 0.f) + ((v3.z != 0.f) ? 1.f : 0.f);
        cw += ((v0.w != 0.f) ? 1.f : 0.f) + ((v1.w != 0.f) ? 1.f : 0.f)
            + ((v2.w != 0.f) ? 1.f : 0.f) + ((v3.w != 0.f) ? 1.f : 0.f);
    }
    // Tail (general correctness for lengths % 4 != 0)
    for (; t < end; t++, p += D4) {
        float4 v = __ldg(p);
        sx += v.x; sy += v.y; sz += v.z; sw += v.w;
        cx += (v.x != 0.f) ? 1.f : 0.f;
        cy += (v.y != 0.f) ? 1.f : 0.f;
        cz += (v.z != 0.f) ? 1.f : 0.f;
        cw += (v.w != 0.f) ? 1.f : 0.f;
    }

    // Whole-segment emptiness check (seg_cnt.sum(-1) == 0)
    sh_cnt[tid] = cx + cy + cz + cw;
    __syncthreads();
    if (tid == 0) {
        float tot = 0.f;
        #pragma unroll 8
        for (int i = 0; i < 192; i++) tot += sh_cnt[i];
        sh_empty = (tot == 0.f) ? 1 : 0;
    }
    __syncthreads();
    const bool empty = (sh_empty != 0);

    const float lm = (len_mask[b * SS + s] != 0) ? 1.f : 0.f;
    const float rm = (rep_mask[b * SS + s] != 0) ? 1.f : 0.f;

    float4 o;
    if (empty) {
        // fallback to word_vectors[0, 0, :]
        float4 w0 = __ldg(reinterpret_cast<const float4*>(wv) + tid);
        o.x = w0.x * lm; o.y = w0.y * lm; o.z = w0.z * lm; o.w = w0.w * lm;
    } else {
        float dx = (cx == 0.f) ? 1.f : cx;
        float dy = (cy == 0.f) ? 1.f : cy;
        float dz = (cz == 0.f) ? 1.f : cz;
        float dw = (cw == 0.f) ? 1.f : cw;
        o.x = (sx / dx) * lm;
        o.y = (sy / dy) * lm;
        o.z = (sz / dz) * lm;
        o.w = (sw / dw) * lm;
    }
    // mean_vec goes to out[b, S + s, :]
    float4* out4 = reinterpret_cast<float4*>(out);
    out4[((size_t)b * 2 * SS + SS + s) * D4 + tid] = o;

    // rep_vec: gather word_vectors[b, rep_ids[b,s], :] * rep_mask
    int rid = rep_ids[b * SS + s];
    if (rid < 0) rid = 0;
    if (rid >= TT) rid = TT - 1;
    float4 r = __ldg(base + (size_t)rid * D4 + tid);
    r.x *= rm; r.y *= rm; r.z *= rm; r.w *= rm;
    out4[((size_t)b * 2 * SS + s) * D4 + tid] = r;

    // output mask tail (flattened tuple): out_tail[b, c] with c in [0, 2S)
    if (write_mask_tail) {
        float* out_tail = out + OUT_VEC;
        if (tid == 0) out_tail[b * 2 * SS + s]      = rm;   // rep mask half
        if (tid == 1) out_tail[b * 2 * SS + SS + s] = lm;   // len mask half
    }
}

extern "C" void kernel_launch(void* const* d_in, const int* in_sizes, int n_in,
                              void* d_out, int out_size)
{
    const float* wv       = (const float*)d_in[0];
    const int*   rep_ids  = (const int*)d_in[1];
    const int*   rep_mask = (const int*)d_in[2];
    const int*   lens     = (const int*)d_in[3];
    const int*   len_mask = (const int*)d_in[4];
    float* out = (float*)d_out;

    int write_mask_tail = ((size_t)out_size > OUT_VEC) ? 1 : 0;
    pooling_kernel<<<BB * SS, 192>>>(wv, rep_ids, rep_mask, lens, len_mask, out,
                                     write_mask_tail);
}

// round 5
// speedup vs baseline: 1.1534x; 1.0548x over previous
#include <cuda_runtime.h>
#include <cstdint>

// Problem constants (from reference setup_inputs)
#define BB 16
#define TT 4096
#define DD 768
#define SS 64
#define D4 (DD / 4)          // 192 float4 lanes per row
#define OUT_VEC ((size_t)BB * 2 * SS * DD)   // 1,572,864 floats

// One block per (b, s) segment. 192 threads; thread tid owns float4 column tid.
// Token loop is batched x4 (independent LDG.128s, MLP=4); streaming loads use
// evict-first (__ldcs) since each byte is read exactly once.
__global__ __launch_bounds__(192, 7) void pooling_kernel(
    const float* __restrict__ wv,           // [B, T, D]
    const int* __restrict__ rep_ids,        // [B, S]
    const int* __restrict__ rep_mask,       // [B, S] bool marshaled as int32
    const int* __restrict__ lens,           // [B, S]
    const int* __restrict__ len_mask,       // [B, S] bool marshaled as int32
    float* __restrict__ out,                // [B, 2S, D] (+ optional [B, 2S] mask tail)
    int write_mask_tail)
{
    const int blk = blockIdx.x;             // b*S + s
    const int b = blk / SS;
    const int s = blk % SS;
    const int tid = threadIdx.x;            // 0..191

    __shared__ int sh_bounds[2];
    __shared__ float sh_cnt[192];
    __shared__ int sh_empty;

    if (tid == 0) {
        const int* lrow = lens + b * SS;
        int start = 0;
        #pragma unroll 8
        for (int i = 0; i < SS; i++) {
            int li = lrow[i];
            if (i < s) start += li;
        }
        long long endl = (long long)start + (long long)lrow[s];
        if (start < 0) start = 0;
        if (start > TT) start = TT;
        int end = (endl > TT) ? TT : (int)endl;
        if (end < start) end = start;
        sh_bounds[0] = start;
        sh_bounds[1] = end;
    }
    __syncthreads();
    const int start = sh_bounds[0];
    const int end   = sh_bounds[1];

    const float4* base = reinterpret_cast<const float4*>(wv + (size_t)b * TT * DD);
    const float4* p = base + (size_t)start * D4 + tid;

    float sx = 0.f, sy = 0.f, sz = 0.f, sw = 0.f;
    float cx = 0.f, cy = 0.f, cz = 0.f, cw = 0.f;

    int t = start;
    // Main loop: 4 tokens per iteration, 4 independent LDG.128.CS in flight.
    for (; t + 4 <= end; t += 4, p += 4 * D4) {
        float4 v0 = __ldcs(p);
        float4 v1 = __ldcs(p + D4);
        float4 v2 = __ldcs(p + 2 * D4);
        float4 v3 = __ldcs(p + 3 * D4);

        sx += v0.x + v1.x + v2.x + v3.x;
        sy += v0.y + v1.y + v2.y + v3.y;
        sz += v0.z + v1.z + v2.z + v3.z;
        sw += v0.w + v1.w + v2.w + v3.w;

        cx += ((v0.x != 0.f) ? 1.f : 0.f) + ((v1.x != 0.f) ? 1.f : 0.f)
            + ((v2.x != 0.f) ? 1.f : 0.f) + ((v3.x != 0.f) ? 1.f : 0.f);
        cy += ((v0.y != 0.f) ? 1.f : 0.f) + ((v1.y != 0.f) ? 1.f : 0.f)
            + ((v2.y != 0.f) ? 1.f : 0.f) + ((v3.y != 0.f) ? 1.f : 0.f);
        cz += ((v0.z != 0.f) ? 1.f : 0.f) + ((v1.z != 0.f) ? 1.f : 0.f)
            + ((v2.z != 0.f) ? 1.f : 0.f) + ((v3.z != 0.f) ? 1.f : 0.f);
        cw += ((v0.w != 0.f) ? 1.f : 0.f) + ((v1.w != 0.f) ? 1.f : 0.f)
            + ((v2.w != 0.f) ? 1.f : 0.f) + ((v3.w != 0.f) ? 1.f : 0.f);
    }
    // Tail (general correctness for lengths % 4 != 0)
    for (; t < end; t++, p += D4) {
        float4 v = __ldcs(p);
        sx += v.x; sy += v.y; sz += v.z; sw += v.w;
        cx += (v.x != 0.f) ? 1.f : 0.f;
        cy += (v.y != 0.f) ? 1.f : 0.f;
        cz += (v.z != 0.f) ? 1.f : 0.f;
        cw += (v.w != 0.f) ? 1.f : 0.f;
    }

    // Whole-segment emptiness check (seg_cnt.sum(-1) == 0)
    sh_cnt[tid] = cx + cy + cz + cw;
    __syncthreads();
    if (tid == 0) {
        float tot = 0.f;
        #pragma unroll 8
        for (int i = 0; i < 192; i++) tot += sh_cnt[i];
        sh_empty = (tot == 0.f) ? 1 : 0;
    }
    __syncthreads();
    const bool empty = (sh_empty != 0);

    const float lm = (len_mask[b * SS + s] != 0) ? 1.f : 0.f;
    const float rm = (rep_mask[b * SS + s] != 0) ? 1.f : 0.f;

    float4 o;
    if (empty) {
        // fallback to word_vectors[0, 0, :]
        float4 w0 = __ldg(reinterpret_cast<const float4*>(wv) + tid);
        o.x = w0.x * lm; o.y = w0.y * lm; o.z = w0.z * lm; o.w = w0.w * lm;
    } else {
        float dx = (cx == 0.f) ? 1.f : cx;
        float dy = (cy == 0.f) ? 1.f : cy;
        float dz = (cz == 0.f) ? 1.f : cz;
        float dw = (cw == 0.f) ? 1.f : cw;
        o.x = (sx / dx) * lm;
        o.y = (sy / dy) * lm;
        o.z = (sz / dz) * lm;
        o.w = (sw / dw) * lm;
    }
    // mean_vec goes to out[b, S + s, :]  (write-once -> streaming store)
    float4* out4 = reinterpret_cast<float4*>(out);
    __stcs(&out4[((size_t)b * 2 * SS + SS + s) * D4 + tid], o);

    // rep_vec: gather word_vectors[b, rep_ids[b,s], :] * rep_mask
    // (likely an L2 hit: the rep row lies inside this block's streamed span)
    int rid = rep_ids[b * SS + s];
    if (rid < 0) rid = 0;
    if (rid >= TT) rid = TT - 1;
    float4 r = __ldg(base + (size_t)rid * D4 + tid);
    r.x *= rm; r.y *= rm; r.z *= rm; r.w *= rm;
    __stcs(&out4[((size_t)b * 2 * SS + s) * D4 + tid], r);

    // output mask tail (flattened tuple): out_tail[b, c] with c in [0, 2S)
    if (write_mask_tail) {
        float* out_tail = out + OUT_VEC;
        if (tid == 0) out_tail[b * 2 * SS + s]      = rm;   // rep mask half
        if (tid == 1) out_tail[b * 2 * SS + SS + s] = lm;   // len mask half
    }
}

extern "C" void kernel_launch(void* const* d_in, const int* in_sizes, int n_in,
                              void* d_out, int out_size)
{
    const float* wv       = (const float*)d_in[0];
    const int*   rep_ids  = (const int*)d_in[1];
    const int*   rep_mask = (const int*)d_in[2];
    const int*   lens     = (const int*)d_in[3];
    const int*   len_mask = (const int*)d_in[4];
    float* out = (float*)d_out;

    int write_mask_tail = ((size_t)out_size > OUT_VEC) ? 1 : 0;
    pooling_kernel<<<BB * SS, 192>>>(wv, rep_ids, rep_mask, lens, len_mask, out,
                                     write_mask_tail);
}